// round 14
// baseline (speedup 1.0000x reference)
#include <cuda_runtime.h>
#include <cuda_bf16.h>
#include <cstdint>

// Problem constants (shapes fixed by dataset)
#define NMAX  50000
#define EMAX  1600000
#define RREL  8
#define INF   128

// ---------------- scratch (static device globals; no allocs) ----------------
__device__ __align__(256) float g_xw[(size_t)RREL * NMAX * 64];
__device__ __align__(256) float g_h[(size_t)NMAX * 64];
__device__ __align__(256) int   g_cnt[NMAX * RREL];
__device__ __align__(256) int2  g_sp[EMAX];             // relation-major CSR {gatherOff, inv bits}
__device__ __align__(256) int   g_off[NMAX * RREL + 1];
__device__ __align__(256) int   g_cur[NMAX * RREL];
__device__ __align__(256) int   g_bsum[512];
__device__ __align__(256) __nv_bfloat16 g_xhi[(size_t)NMAX * INF];
__device__ __align__(256) __nv_bfloat16 g_xlo[(size_t)NMAX * INF];
__device__ __align__(256) __nv_bfloat16 g_bhi1[9 * 64 * 128];
__device__ __align__(256) __nv_bfloat16 g_blo1[9 * 64 * 128];
__device__ __align__(256) __nv_bfloat16 g_bhi2[9 * 64 * 64];
__device__ __align__(256) __nv_bfloat16 g_blo2[9 * 64 * 64];

__device__ __forceinline__ uint32_t smem_u32(const void* p) {
    uint32_t a;
    asm("{ .reg .u64 t; cvta.to.shared.u64 t, %1; cvt.u32.u64 %0, t; }" : "=r"(a) : "l"(p));
    return a;
}
__device__ __forceinline__ void ldsm4(uint32_t* r, uint32_t addr) {
    asm volatile("ldmatrix.sync.aligned.m8n8.x4.shared.b16 {%0,%1,%2,%3}, [%4];"
                 : "=r"(r[0]), "=r"(r[1]), "=r"(r[2]), "=r"(r[3]) : "r"(addr));
}
__device__ __forceinline__ void mma16816(float* c, const uint32_t* a, uint32_t b0, uint32_t b1) {
    asm volatile(
        "mma.sync.aligned.m16n8k16.row.col.f32.bf16.bf16.f32 "
        "{%0,%1,%2,%3}, {%4,%5,%6,%7}, {%8,%9}, {%0,%1,%2,%3};"
        : "+f"(c[0]), "+f"(c[1]), "+f"(c[2]), "+f"(c[3])
        : "r"(a[0]), "r"(a[1]), "r"(a[2]), "r"(a[3]), "r"(b0), "r"(b1));
}

// ---------------- prep: counts ----------------
__global__ void k_zero_cnt(int* __restrict__ cnt, int n) {
    int i = blockIdx.x * blockDim.x + threadIdx.x;
    if (i < n) cnt[i] = 0;
}
__global__ void k_count(const int* __restrict__ ei, const int* __restrict__ et,
                        int* __restrict__ cnt, int E) {
    int e = blockIdx.x * blockDim.x + threadIdx.x;
    if (e >= E) return;
    atomicAdd(&cnt[ei[E + e] * RREL + et[e]], 1);
}

// ---------------- prep: exclusive scan over M = N*R segments (relation-major) ----
// element i = t*N + d  ->  count = cnt[d*RREL + t]
__global__ void k_scan_a(const int* __restrict__ cnt, int* __restrict__ off,
                         int* __restrict__ bsum, int N, int M) {
    __shared__ int s[1024];
    int i = blockIdx.x * 1024 + threadIdx.x;
    int deg = 0;
    if (i < M) {
        int t = i / N;
        int d = i - t * N;
        deg = cnt[d * RREL + t];
    }
    s[threadIdx.x] = deg;
    __syncthreads();
    for (int o = 1; o < 1024; o <<= 1) {
        int v = (threadIdx.x >= o) ? s[threadIdx.x - o] : 0;
        __syncthreads();
        s[threadIdx.x] += v;
        __syncthreads();
    }
    if (i < M) off[i] = s[threadIdx.x] - deg;   // exclusive within block
    if (threadIdx.x == 1023) bsum[blockIdx.x] = s[1023];
}
__global__ void k_scan_b(int* __restrict__ bsum, int nb, int* __restrict__ off, int M) {
    __shared__ int s[512];
    int v = (threadIdx.x < nb) ? bsum[threadIdx.x] : 0;
    s[threadIdx.x] = v;
    __syncthreads();
    for (int o = 1; o < 512; o <<= 1) {
        int u = (threadIdx.x >= o) ? s[threadIdx.x - o] : 0;
        __syncthreads();
        s[threadIdx.x] += u;
        __syncthreads();
    }
    if (threadIdx.x < nb) bsum[threadIdx.x] = s[threadIdx.x] - v;  // exclusive base
    if (threadIdx.x == 511) off[M] = s[511];
}
__global__ void k_scan_c(int* __restrict__ off, int* __restrict__ cur,
                         const int* __restrict__ bsum, int M) {
    int i = blockIdx.x * 1024 + threadIdx.x;
    if (i >= M) return;
    int o = off[i] + bsum[blockIdx.x];
    off[i] = o;
    cur[i] = o;
}

// ---------------- prep: permute edges into relation-major CSR order ----------------
__global__ void k_permute(const int* __restrict__ ei, const int* __restrict__ et,
                          const int* __restrict__ cnt, int* __restrict__ cur,
                          int2* __restrict__ sp, int E, int Nn) {
    int e = blockIdx.x * blockDim.x + threadIdx.x;
    if (e >= E) return;
    int s = ei[e];
    int d = ei[E + e];
    int t = et[e];
    int c = cnt[d * RREL + t];
    float inv = 1.0f / (float)(c > 0 ? c : 1);
    int pos = atomicAdd(&cur[t * Nn + d], 1);
    sp[pos] = make_int2((t * Nn + s) * 64, __float_as_int(inv));
}

// ---------------- fp32 -> bf16 hi/lo split (optionally fused ReLU) ----------------
template<bool RELU>
__global__ void k_split(const float* __restrict__ src, __nv_bfloat16* __restrict__ hi,
                        __nv_bfloat16* __restrict__ lo, int n) {
    int i = blockIdx.x * blockDim.x + threadIdx.x;
    int i4 = i * 4;
    if (i4 >= n) return;
    float4 v = *(const float4*)(src + i4);
    if (RELU) {
        v.x = fmaxf(v.x, 0.f); v.y = fmaxf(v.y, 0.f);
        v.z = fmaxf(v.z, 0.f); v.w = fmaxf(v.w, 0.f);
    }
    float vv[4] = {v.x, v.y, v.z, v.w};
    __nv_bfloat16 h[4], l[4];
#pragma unroll
    for (int j = 0; j < 4; j++) {
        h[j] = __float2bfloat16_rn(vv[j]);
        l[j] = __float2bfloat16_rn(vv[j] - __bfloat162float(h[j]));
    }
    ((__nv_bfloat162*)hi)[i * 2]     = __nv_bfloat162(h[0], h[1]);
    ((__nv_bfloat162*)hi)[i * 2 + 1] = __nv_bfloat162(h[2], h[3]);
    ((__nv_bfloat162*)lo)[i * 2]     = __nv_bfloat162(l[0], l[1]);
    ((__nv_bfloat162*)lo)[i * 2 + 1] = __nv_bfloat162(l[2], l[3]);
}

// ---------------- weight transpose+split: Bt[m][n][k] = W_m[k][n] ----------------
__global__ void k_splitw(const float* __restrict__ Wrel, const float* __restrict__ Wroot,
                         __nv_bfloat16* __restrict__ hi, __nv_bfloat16* __restrict__ lo, int K) {
    int idx = blockIdx.x * blockDim.x + threadIdx.x;
    if (idx >= 9 * 64 * K) return;
    int m = idx / (64 * K);
    int r = idx % (64 * K);
    int n = r / K;
    int k = r % K;
    float w = (m < RREL) ? Wrel[(size_t)m * K * 64 + k * 64 + n] : Wroot[k * 64 + n];
    __nv_bfloat16 h = __float2bfloat16_rn(w);
    hi[idx] = h;
    lo[idx] = __float2bfloat16_rn(w - __bfloat162float(h));
}

// ---------------- HMMA batched skinny GEMM (mma.sync, bf16 3-term split) --------
template<int K>
__global__ void __launch_bounds__(256) k_mma(
    const __nv_bfloat16* __restrict__ Ahi, const __nv_bfloat16* __restrict__ Alo,
    const __nv_bfloat16* __restrict__ Bhi, const __nv_bfloat16* __restrict__ Blo,
    const float* __restrict__ bias, float* __restrict__ Yrel, float* __restrict__ Yroot,
    int Nn)
{
    constexpr int KC  = 64;
    constexpr int LDB = KC + 8;                 // 72 bf16 = 144B row stride
    constexpr int NCH = K / KC;
    constexpr int OAH = 0;
    constexpr int OAL = 128 * LDB;
    constexpr int OBH = 2 * 128 * LDB;
    constexpr int OBL = 2 * 128 * LDB + 64 * LDB;

    extern __shared__ __nv_bfloat16 sm[];
    const uint32_t sb = smem_u32(sm);
    const int tid = threadIdx.x;
    const int w   = tid >> 5;
    const int l   = tid & 31;
    const int m   = blockIdx.y;
    const int row0 = blockIdx.x * 128;

    const __nv_bfloat16* bh = Bhi + (size_t)m * 64 * K;
    const __nv_bfloat16* bl = Blo + (size_t)m * 64 * K;

    const int arow = w * 16 + (l & 15);
    const int acol = (l >> 4) << 3;
    const uint32_t aoffA = (uint32_t)(arow * LDB + acol) * 2;
    const int brow = (l & 7) + ((l >> 4) << 3);
    const int bcol = ((l >> 3) & 1) << 3;
    const uint32_t aoffB = (uint32_t)(brow * LDB + bcol) * 2;

    float acc[8][4];
#pragma unroll
    for (int nb = 0; nb < 8; nb++)
#pragma unroll
        for (int j = 0; j < 4; j++) acc[nb][j] = 0.f;

    for (int kc = 0; kc < NCH; ++kc) {
        if (kc) __syncthreads();
#pragma unroll
        for (int it = 0; it < 4; ++it) {
            int idx = tid + it * 256;
            int r = idx >> 3, c8 = (idx & 7) << 3;
            int grow = row0 + r;
            uint4 vh = make_uint4(0, 0, 0, 0), vl = make_uint4(0, 0, 0, 0);
            if (grow < Nn) {
                vh = *(const uint4*)(Ahi + (size_t)grow * K + kc * KC + c8);
                vl = *(const uint4*)(Alo + (size_t)grow * K + kc * KC + c8);
            }
            *(uint4*)&sm[OAH + r * LDB + c8] = vh;
            *(uint4*)&sm[OAL + r * LDB + c8] = vl;
        }
#pragma unroll
        for (int it = 0; it < 2; ++it) {
            int idx = tid + it * 256;
            int r = idx >> 3, c8 = (idx & 7) << 3;
            *(uint4*)&sm[OBH + r * LDB + c8] = *(const uint4*)(bh + (size_t)r * K + kc * KC + c8);
            *(uint4*)&sm[OBL + r * LDB + c8] = *(const uint4*)(bl + (size_t)r * K + kc * KC + c8);
        }
        __syncthreads();

#pragma unroll
        for (int ks = 0; ks < KC / 16; ++ks) {
            const uint32_t kb = ks * 32;
            uint32_t ah[4], al[4];
            ldsm4(ah, sb + (OAH * 2) + aoffA + kb);
            ldsm4(al, sb + (OAL * 2) + aoffA + kb);
#pragma unroll
            for (int p = 0; p < 4; ++p) {
                uint32_t bhf[4], blf[4];
                const uint32_t bo = (uint32_t)(p * 16 * LDB) * 2 + kb;
                ldsm4(bhf, sb + (OBH * 2) + aoffB + bo);
                ldsm4(blf, sb + (OBL * 2) + aoffB + bo);
                mma16816(acc[2 * p],     ah, bhf[0], bhf[1]);
                mma16816(acc[2 * p + 1], ah, bhf[2], bhf[3]);
                mma16816(acc[2 * p],     ah, blf[0], blf[1]);
                mma16816(acc[2 * p + 1], ah, blf[2], blf[3]);
                mma16816(acc[2 * p],     al, bhf[0], bhf[1]);
                mma16816(acc[2 * p + 1], al, bhf[2], bhf[3]);
            }
        }
    }

    float* Y = (m < RREL) ? (Yrel + (size_t)m * Nn * 64) : Yroot;
    const bool useBias = (m == RREL);
    const int rA = row0 + w * 16 + (l >> 2);
    const int c0 = (l & 3) * 2;
#pragma unroll
    for (int nb = 0; nb < 8; ++nb) {
        int col = nb * 8 + c0;
        float bx = 0.f, by = 0.f;
        if (useBias) { bx = bias[col]; by = bias[col + 1]; }
        if (rA < Nn)
            *(float2*)(Y + (size_t)rA * 64 + col) = make_float2(acc[nb][0] + bx, acc[nb][1] + by);
        if (rA + 8 < Nn)
            *(float2*)(Y + (size_t)(rA + 8) * 64 + col) = make_float2(acc[nb][2] + bx, acc[nb][3] + by);
    }
}

// ---------------- relation-major CSR aggregation ----------------
// Segment g = t*N + d; 16 lanes per segment accumulate in registers, then one
// red.global.add.v4 into the root-initialized output. Relation-major grid order
// keeps each relation's 12.8MB gather slice L2-resident during its wave.
__global__ void __launch_bounds__(256) k_agg(
    const int* __restrict__ off, const int2* __restrict__ sp,
    const float* __restrict__ xw, float* __restrict__ out, int Nn, int M)
{
    int g = blockIdx.x * 16 + (threadIdx.x >> 4);
    if (g >= M) return;
    int lane = (threadIdx.x & 15) << 2;

    int beg = __ldg(&off[g]);
    int end = __ldg(&off[g + 1]);
    if (beg == end) return;

    float4 acc = make_float4(0.f, 0.f, 0.f, 0.f);

    int e = beg;
    int e4 = beg + ((end - beg) & ~3);
    for (; e < e4; e += 4) {
        int2 p0 = __ldg(&sp[e]);
        int2 p1 = __ldg(&sp[e + 1]);
        int2 p2 = __ldg(&sp[e + 2]);
        int2 p3 = __ldg(&sp[e + 3]);
        float4 v0 = __ldg((const float4*)(xw + p0.x + lane));
        float4 v1 = __ldg((const float4*)(xw + p1.x + lane));
        float4 v2 = __ldg((const float4*)(xw + p2.x + lane));
        float4 v3 = __ldg((const float4*)(xw + p3.x + lane));
        float i0 = __int_as_float(p0.y), i1 = __int_as_float(p1.y);
        float i2 = __int_as_float(p2.y), i3 = __int_as_float(p3.y);
        acc.x = fmaf(v0.x, i0, acc.x); acc.y = fmaf(v0.y, i0, acc.y);
        acc.z = fmaf(v0.z, i0, acc.z); acc.w = fmaf(v0.w, i0, acc.w);
        acc.x = fmaf(v1.x, i1, acc.x); acc.y = fmaf(v1.y, i1, acc.y);
        acc.z = fmaf(v1.z, i1, acc.z); acc.w = fmaf(v1.w, i1, acc.w);
        acc.x = fmaf(v2.x, i2, acc.x); acc.y = fmaf(v2.y, i2, acc.y);
        acc.z = fmaf(v2.z, i2, acc.z); acc.w = fmaf(v2.w, i2, acc.w);
        acc.x = fmaf(v3.x, i3, acc.x); acc.y = fmaf(v3.y, i3, acc.y);
        acc.z = fmaf(v3.z, i3, acc.z); acc.w = fmaf(v3.w, i3, acc.w);
    }
    for (; e < end; ++e) {
        int2 p = __ldg(&sp[e]);
        float4 v = __ldg((const float4*)(xw + p.x + lane));
        float iv = __int_as_float(p.y);
        acc.x = fmaf(v.x, iv, acc.x); acc.y = fmaf(v.y, iv, acc.y);
        acc.z = fmaf(v.z, iv, acc.z); acc.w = fmaf(v.w, iv, acc.w);
    }

    int d = g % Nn;
    float* addr = out + (size_t)d * 64 + lane;
    asm volatile("red.global.add.v4.f32 [%0], {%1,%2,%3,%4};"
                 :: "l"(addr), "f"(acc.x), "f"(acc.y), "f"(acc.z), "f"(acc.w)
                 : "memory");
}

// ---------------- launch ----------------
extern "C" void kernel_launch(void* const* d_in, const int* in_sizes, int n_in,
                              void* d_out, int out_size) {
    const float* x       = (const float*)d_in[0];
    const int*   ei      = (const int*)d_in[1];   // int32 (JAX x64 disabled)
    const int*   et      = (const int*)d_in[2];
    const float* W1_rel  = (const float*)d_in[3];
    const float* W1_root = (const float*)d_in[4];
    const float* b1      = (const float*)d_in[5];
    const float* W2_rel  = (const float*)d_in[6];
    const float* W2_root = (const float*)d_in[7];
    const float* b2      = (const float*)d_in[8];
    float* out = (float*)d_out;

    const int N = in_sizes[0] / INF;
    const int E = in_sizes[2];
    const int M = N * RREL;

    float *xw, *h;
    int *cnt, *offp, *curp, *bsum;
    int2 *sp;
    __nv_bfloat16 *xhi, *xlo, *bh1, *bl1, *bh2, *bl2;
    cudaGetSymbolAddress((void**)&xw,   g_xw);
    cudaGetSymbolAddress((void**)&h,    g_h);
    cudaGetSymbolAddress((void**)&cnt,  g_cnt);
    cudaGetSymbolAddress((void**)&sp,   g_sp);
    cudaGetSymbolAddress((void**)&offp, g_off);
    cudaGetSymbolAddress((void**)&curp, g_cur);
    cudaGetSymbolAddress((void**)&bsum, g_bsum);
    cudaGetSymbolAddress((void**)&xhi,  g_xhi);
    cudaGetSymbolAddress((void**)&xlo,  g_xlo);
    cudaGetSymbolAddress((void**)&bh1,  g_bhi1);
    cudaGetSymbolAddress((void**)&bl1,  g_blo1);
    cudaGetSymbolAddress((void**)&bh2,  g_bhi2);
    cudaGetSymbolAddress((void**)&bl2,  g_blo2);

    const int SMB = (2 * 128 + 2 * 64) * 72 * 2;  // 55296 B
    cudaFuncSetAttribute(k_mma<128>, cudaFuncAttributeMaxDynamicSharedMemorySize, SMB);
    cudaFuncSetAttribute(k_mma<64>,  cudaFuncAttributeMaxDynamicSharedMemorySize, SMB);

    // high-priority side stream + fork/join events (created once, host-side only)
    static cudaStream_t s1 = nullptr;
    static cudaEvent_t evFork = nullptr, evJoin = nullptr;
    if (!s1) {
        int loPri, hiPri;
        cudaDeviceGetStreamPriorityRange(&loPri, &hiPri);
        cudaStreamCreateWithPriority(&s1, cudaStreamNonBlocking, hiPri);
        cudaEventCreateWithFlags(&evFork, cudaEventDisableTiming);
        cudaEventCreateWithFlags(&evJoin, cudaEventDisableTiming);
    }

    const int nscan = (M + 1023) / 1024;   // 391 blocks (fits 512-wide level-2 scan)
    dim3 gg((N + 127) / 128, 9);
    const int ab = (M + 15) / 16;

    // ---- fork: CSR build + layer-2 weight split on high-priority s1 ----
    cudaEventRecord(evFork, 0);
    cudaStreamWaitEvent(s1, evFork, 0);

    k_zero_cnt<<<(M + 255) / 256, 256, 0, s1>>>(cnt, M);
    k_count<<<(E + 255) / 256, 256, 0, s1>>>(ei, et, cnt, E);
    k_scan_a<<<nscan, 1024, 0, s1>>>(cnt, offp, bsum, N, M);
    k_scan_b<<<1, 512, 0, s1>>>(bsum, nscan, offp, M);
    k_scan_c<<<nscan, 1024, 0, s1>>>(offp, curp, bsum, M);
    k_permute<<<(E + 255) / 256, 256, 0, s1>>>(ei, et, cnt, curp, sp, E, N);
    k_splitw<<<(9 * 64 * 64 + 255) / 256, 256, 0, s1>>>(W2_rel, W2_root, bh2, bl2, 64);
    cudaEventRecord(evJoin, s1);

    // ---- main stream: layer-1 weight split, input split, transforms ----
    k_splitw<<<(9 * 64 * 128 + 255) / 256, 256>>>(W1_rel, W1_root, bh1, bl1, 128);
    k_split<false><<<(N * 128 / 4 + 255) / 256, 256>>>(x, xhi, xlo, N * 128);
    k_mma<128><<<gg, 256, SMB>>>(xhi, xlo, bh1, bl1, b1, xw, h, N);

    // ---- join: aggregation needs CSR + xw/h ----
    cudaStreamWaitEvent(0, evJoin, 0);
    k_agg<<<ab, 256>>>(offp, sp, xw, h, N, M);

    // Layer 2: ReLU fused into split; root init of d_out; aggregation
    k_split<true><<<(N * 64 / 4 + 255) / 256, 256>>>(h, xhi, xlo, N * 64);
    k_mma<64><<<gg, 256, SMB>>>(xhi, xlo, bh2, bl2, b2, xw, out, N);
    k_agg<<<ab, 256>>>(offp, sp, xw, out, N, M);
}

// round 15
// speedup vs baseline: 1.5000x; 1.5000x over previous
#include <cuda_runtime.h>
#include <cuda_bf16.h>
#include <cuda_fp16.h>
#include <cstdint>

// Problem constants (shapes fixed by dataset)
#define NMAX  50000
#define EMAX  1600000
#define RREL  8
#define INF   128

// ---------------- scratch (static device globals; no allocs) ----------------
__device__ __align__(256) __half g_xw[(size_t)RREL * NMAX * 64];   // fp16 messages
__device__ __align__(256) float g_h[(size_t)NMAX * 64];
__device__ __align__(256) int   g_cnt[NMAX * RREL];
__device__ __align__(256) int2  g_sp[EMAX];        // dst-CSR {gatherOff, inv bits}
__device__ __align__(256) int   g_off[NMAX + 1];
__device__ __align__(256) int   g_cur[NMAX];
__device__ __align__(256) int   g_bsum[64];
__device__ __align__(256) __nv_bfloat16 g_xhi[(size_t)NMAX * INF];
__device__ __align__(256) __nv_bfloat16 g_xlo[(size_t)NMAX * INF];
__device__ __align__(256) __nv_bfloat16 g_bhi1[9 * 64 * 128];
__device__ __align__(256) __nv_bfloat16 g_blo1[9 * 64 * 128];
__device__ __align__(256) __nv_bfloat16 g_bhi2[9 * 64 * 64];
__device__ __align__(256) __nv_bfloat16 g_blo2[9 * 64 * 64];

__device__ __forceinline__ uint32_t smem_u32(const void* p) {
    uint32_t a;
    asm("{ .reg .u64 t; cvta.to.shared.u64 t, %1; cvt.u32.u64 %0, t; }" : "=r"(a) : "l"(p));
    return a;
}
__device__ __forceinline__ void ldsm4(uint32_t* r, uint32_t addr) {
    asm volatile("ldmatrix.sync.aligned.m8n8.x4.shared.b16 {%0,%1,%2,%3}, [%4];"
                 : "=r"(r[0]), "=r"(r[1]), "=r"(r[2]), "=r"(r[3]) : "r"(addr));
}
__device__ __forceinline__ void mma16816(float* c, const uint32_t* a, uint32_t b0, uint32_t b1) {
    asm volatile(
        "mma.sync.aligned.m16n8k16.row.col.f32.bf16.bf16.f32 "
        "{%0,%1,%2,%3}, {%4,%5,%6,%7}, {%8,%9}, {%0,%1,%2,%3};"
        : "+f"(c[0]), "+f"(c[1]), "+f"(c[2]), "+f"(c[3])
        : "r"(a[0]), "r"(a[1]), "r"(a[2]), "r"(a[3]), "r"(b0), "r"(b1));
}

// ---------------- prep: counts ----------------
__global__ void k_zero_cnt(int* __restrict__ cnt, int n) {
    int i = blockIdx.x * blockDim.x + threadIdx.x;
    if (i < n) cnt[i] = 0;
}
__global__ void k_count(const int* __restrict__ ei, const int* __restrict__ et,
                        int* __restrict__ cnt, int E) {
    int e = blockIdx.x * blockDim.x + threadIdx.x;
    if (e >= E) return;
    atomicAdd(&cnt[ei[E + e] * RREL + et[e]], 1);
}

// ---------------- prep: exclusive scan of per-dst degrees (3 kernels) ----------------
__global__ void k_scan_a(const int* __restrict__ cnt, int* __restrict__ off,
                         int* __restrict__ bsum, int N) {
    __shared__ int s[1024];
    int d = blockIdx.x * 1024 + threadIdx.x;
    int deg = 0;
    if (d < N) {
        int4 a = ((const int4*)cnt)[d * 2];
        int4 b = ((const int4*)cnt)[d * 2 + 1];
        deg = a.x + a.y + a.z + a.w + b.x + b.y + b.z + b.w;
    }
    s[threadIdx.x] = deg;
    __syncthreads();
    for (int o = 1; o < 1024; o <<= 1) {
        int v = (threadIdx.x >= o) ? s[threadIdx.x - o] : 0;
        __syncthreads();
        s[threadIdx.x] += v;
        __syncthreads();
    }
    if (d < N) off[d] = s[threadIdx.x] - deg;   // exclusive within block
    if (threadIdx.x == 1023) bsum[blockIdx.x] = s[1023];
}
__global__ void k_scan_b(int* __restrict__ bsum, int nb, int* __restrict__ off, int N) {
    __shared__ int s[64];
    int v = (threadIdx.x < nb) ? bsum[threadIdx.x] : 0;
    s[threadIdx.x] = v;
    __syncthreads();
    for (int o = 1; o < 64; o <<= 1) {
        int u = (threadIdx.x >= o) ? s[threadIdx.x - o] : 0;
        __syncthreads();
        s[threadIdx.x] += u;
        __syncthreads();
    }
    if (threadIdx.x < nb) bsum[threadIdx.x] = s[threadIdx.x] - v;  // exclusive base
    if (threadIdx.x == 63) off[N] = s[63];
}
__global__ void k_scan_c(int* __restrict__ off, int* __restrict__ cur,
                         const int* __restrict__ bsum, int N) {
    int d = blockIdx.x * 1024 + threadIdx.x;
    if (d >= N) return;
    int o = off[d] + bsum[blockIdx.x];
    off[d] = o;
    cur[d] = o;
}

// ---------------- prep: permute edges into dst-CSR order ----------------
__global__ void k_permute(const int* __restrict__ ei, const int* __restrict__ et,
                          const int* __restrict__ cnt, int* __restrict__ cur,
                          int2* __restrict__ sp, int E, int Nn) {
    int e = blockIdx.x * blockDim.x + threadIdx.x;
    if (e >= E) return;
    int s = ei[e];
    int d = ei[E + e];
    int t = et[e];
    int c = cnt[d * RREL + t];
    float inv = 1.0f / (float)(c > 0 ? c : 1);
    int pos = atomicAdd(&cur[d], 1);
    sp[pos] = make_int2((t * Nn + s) * 64, __float_as_int(inv));
}

// ---------------- fp32 -> bf16 hi/lo split (optionally fused ReLU) ----------------
template<bool RELU>
__global__ void k_split(const float* __restrict__ src, __nv_bfloat16* __restrict__ hi,
                        __nv_bfloat16* __restrict__ lo, int n) {
    int i = blockIdx.x * blockDim.x + threadIdx.x;
    int i4 = i * 4;
    if (i4 >= n) return;
    float4 v = *(const float4*)(src + i4);
    if (RELU) {
        v.x = fmaxf(v.x, 0.f); v.y = fmaxf(v.y, 0.f);
        v.z = fmaxf(v.z, 0.f); v.w = fmaxf(v.w, 0.f);
    }
    float vv[4] = {v.x, v.y, v.z, v.w};
    __nv_bfloat16 h[4], l[4];
#pragma unroll
    for (int j = 0; j < 4; j++) {
        h[j] = __float2bfloat16_rn(vv[j]);
        l[j] = __float2bfloat16_rn(vv[j] - __bfloat162float(h[j]));
    }
    ((__nv_bfloat162*)hi)[i * 2]     = __nv_bfloat162(h[0], h[1]);
    ((__nv_bfloat162*)hi)[i * 2 + 1] = __nv_bfloat162(h[2], h[3]);
    ((__nv_bfloat162*)lo)[i * 2]     = __nv_bfloat162(l[0], l[1]);
    ((__nv_bfloat162*)lo)[i * 2 + 1] = __nv_bfloat162(l[2], l[3]);
}

// ---------------- weight transpose+split: Bt[m][n][k] = W_m[k][n] ----------------
__global__ void k_splitw(const float* __restrict__ Wrel, const float* __restrict__ Wroot,
                         __nv_bfloat16* __restrict__ hi, __nv_bfloat16* __restrict__ lo, int K) {
    int idx = blockIdx.x * blockDim.x + threadIdx.x;
    if (idx >= 9 * 64 * K) return;
    int m = idx / (64 * K);
    int r = idx % (64 * K);
    int n = r / K;
    int k = r % K;
    float w = (m < RREL) ? Wrel[(size_t)m * K * 64 + k * 64 + n] : Wroot[k * 64 + n];
    __nv_bfloat16 h = __float2bfloat16_rn(w);
    hi[idx] = h;
    lo[idx] = __float2bfloat16_rn(w - __bfloat162float(h));
}

// ---------------- HMMA batched skinny GEMM (mma.sync, bf16 3-term split) --------
// m<8: write fp16 messages into Yrel; m==8: write fp32 root (+bias) into Yroot.
template<int K>
__global__ void __launch_bounds__(256) k_mma(
    const __nv_bfloat16* __restrict__ Ahi, const __nv_bfloat16* __restrict__ Alo,
    const __nv_bfloat16* __restrict__ Bhi, const __nv_bfloat16* __restrict__ Blo,
    const float* __restrict__ bias, __half* __restrict__ Yrel, float* __restrict__ Yroot,
    int Nn)
{
    constexpr int KC  = 64;
    constexpr int LDB = KC + 8;                 // 72 bf16 = 144B row stride
    constexpr int NCH = K / KC;
    constexpr int OAH = 0;
    constexpr int OAL = 128 * LDB;
    constexpr int OBH = 2 * 128 * LDB;
    constexpr int OBL = 2 * 128 * LDB + 64 * LDB;

    extern __shared__ __nv_bfloat16 sm[];
    const uint32_t sb = smem_u32(sm);
    const int tid = threadIdx.x;
    const int w   = tid >> 5;
    const int l   = tid & 31;
    const int m   = blockIdx.y;
    const int row0 = blockIdx.x * 128;

    const __nv_bfloat16* bh = Bhi + (size_t)m * 64 * K;
    const __nv_bfloat16* bl = Blo + (size_t)m * 64 * K;

    const int arow = w * 16 + (l & 15);
    const int acol = (l >> 4) << 3;
    const uint32_t aoffA = (uint32_t)(arow * LDB + acol) * 2;
    const int brow = (l & 7) + ((l >> 4) << 3);
    const int bcol = ((l >> 3) & 1) << 3;
    const uint32_t aoffB = (uint32_t)(brow * LDB + bcol) * 2;

    float acc[8][4];
#pragma unroll
    for (int nb = 0; nb < 8; nb++)
#pragma unroll
        for (int j = 0; j < 4; j++) acc[nb][j] = 0.f;

    for (int kc = 0; kc < NCH; ++kc) {
        if (kc) __syncthreads();
#pragma unroll
        for (int it = 0; it < 4; ++it) {
            int idx = tid + it * 256;
            int r = idx >> 3, c8 = (idx & 7) << 3;
            int grow = row0 + r;
            uint4 vh = make_uint4(0, 0, 0, 0), vl = make_uint4(0, 0, 0, 0);
            if (grow < Nn) {
                vh = *(const uint4*)(Ahi + (size_t)grow * K + kc * KC + c8);
                vl = *(const uint4*)(Alo + (size_t)grow * K + kc * KC + c8);
            }
            *(uint4*)&sm[OAH + r * LDB + c8] = vh;
            *(uint4*)&sm[OAL + r * LDB + c8] = vl;
        }
#pragma unroll
        for (int it = 0; it < 2; ++it) {
            int idx = tid + it * 256;
            int r = idx >> 3, c8 = (idx & 7) << 3;
            *(uint4*)&sm[OBH + r * LDB + c8] = *(const uint4*)(bh + (size_t)r * K + kc * KC + c8);
            *(uint4*)&sm[OBL + r * LDB + c8] = *(const uint4*)(bl + (size_t)r * K + kc * KC + c8);
        }
        __syncthreads();

#pragma unroll
        for (int ks = 0; ks < KC / 16; ++ks) {
            const uint32_t kb = ks * 32;
            uint32_t ah[4], al[4];
            ldsm4(ah, sb + (OAH * 2) + aoffA + kb);
            ldsm4(al, sb + (OAL * 2) + aoffA + kb);
#pragma unroll
            for (int p = 0; p < 4; ++p) {
                uint32_t bhf[4], blf[4];
                const uint32_t bo = (uint32_t)(p * 16 * LDB) * 2 + kb;
                ldsm4(bhf, sb + (OBH * 2) + aoffB + bo);
                ldsm4(blf, sb + (OBL * 2) + aoffB + bo);
                mma16816(acc[2 * p],     ah, bhf[0], bhf[1]);
                mma16816(acc[2 * p + 1], ah, bhf[2], bhf[3]);
                mma16816(acc[2 * p],     ah, blf[0], blf[1]);
                mma16816(acc[2 * p + 1], ah, blf[2], blf[3]);
                mma16816(acc[2 * p],     al, bhf[0], bhf[1]);
                mma16816(acc[2 * p + 1], al, bhf[2], bhf[3]);
            }
        }
    }

    const int rA = row0 + w * 16 + (l >> 2);
    const int c0 = (l & 3) * 2;
    if (m < RREL) {
        __half* Y = Yrel + (size_t)m * Nn * 64;
#pragma unroll
        for (int nb = 0; nb < 8; ++nb) {
            int col = nb * 8 + c0;
            if (rA < Nn)
                *(__half2*)(Y + (size_t)rA * 64 + col) =
                    __floats2half2_rn(acc[nb][0], acc[nb][1]);
            if (rA + 8 < Nn)
                *(__half2*)(Y + (size_t)(rA + 8) * 64 + col) =
                    __floats2half2_rn(acc[nb][2], acc[nb][3]);
        }
    } else {
#pragma unroll
        for (int nb = 0; nb < 8; ++nb) {
            int col = nb * 8 + c0;
            float bx = bias[col], by = bias[col + 1];
            if (rA < Nn)
                *(float2*)(Yroot + (size_t)rA * 64 + col) =
                    make_float2(acc[nb][0] + bx, acc[nb][1] + by);
            if (rA + 8 < Nn)
                *(float2*)(Yroot + (size_t)(rA + 8) * 64 + col) =
                    make_float2(acc[nb][2] + bx, acc[nb][3] + by);
        }
    }
}

// ---------------- CSR aggregation (no atomics), fp16 gathers, 4-wide unrolled ----
__global__ void __launch_bounds__(256) k_agg(
    const int* __restrict__ off, const int2* __restrict__ sp,
    const __half* __restrict__ xw, float* __restrict__ out, int Nn)
{
    int d = blockIdx.x * 16 + (threadIdx.x >> 4);
    if (d >= Nn) return;
    int lane = (threadIdx.x & 15) << 2;   // 4 halves per lane (8 bytes)

    int beg = __ldg(&off[d]);
    int end = __ldg(&off[d + 1]);

    float* yp = out + (size_t)d * 64 + lane;
    float4 acc = *(float4*)yp;

    int e = beg;
    int e4 = beg + ((end - beg) & ~3);
    for (; e < e4; e += 4) {
        int2 p0 = __ldg(&sp[e]);
        int2 p1 = __ldg(&sp[e + 1]);
        int2 p2 = __ldg(&sp[e + 2]);
        int2 p3 = __ldg(&sp[e + 3]);
        uint2 u0 = __ldg((const uint2*)(xw + p0.x + lane));
        uint2 u1 = __ldg((const uint2*)(xw + p1.x + lane));
        uint2 u2 = __ldg((const uint2*)(xw + p2.x + lane));
        uint2 u3 = __ldg((const uint2*)(xw + p3.x + lane));
        float i0 = __int_as_float(p0.y), i1 = __int_as_float(p1.y);
        float i2 = __int_as_float(p2.y), i3 = __int_as_float(p3.y);
        float2 a0 = __half22float2(*(__half2*)&u0.x), b0 = __half22float2(*(__half2*)&u0.y);
        float2 a1 = __half22float2(*(__half2*)&u1.x), b1 = __half22float2(*(__half2*)&u1.y);
        float2 a2 = __half22float2(*(__half2*)&u2.x), b2 = __half22float2(*(__half2*)&u2.y);
        float2 a3 = __half22float2(*(__half2*)&u3.x), b3 = __half22float2(*(__half2*)&u3.y);
        acc.x = fmaf(a0.x, i0, acc.x); acc.y = fmaf(a0.y, i0, acc.y);
        acc.z = fmaf(b0.x, i0, acc.z); acc.w = fmaf(b0.y, i0, acc.w);
        acc.x = fmaf(a1.x, i1, acc.x); acc.y = fmaf(a1.y, i1, acc.y);
        acc.z = fmaf(b1.x, i1, acc.z); acc.w = fmaf(b1.y, i1, acc.w);
        acc.x = fmaf(a2.x, i2, acc.x); acc.y = fmaf(a2.y, i2, acc.y);
        acc.z = fmaf(b2.x, i2, acc.z); acc.w = fmaf(b2.y, i2, acc.w);
        acc.x = fmaf(a3.x, i3, acc.x); acc.y = fmaf(a3.y, i3, acc.y);
        acc.z = fmaf(b3.x, i3, acc.z); acc.w = fmaf(b3.y, i3, acc.w);
    }
    for (; e < end; ++e) {
        int2 p = __ldg(&sp[e]);
        uint2 u = __ldg((const uint2*)(xw + p.x + lane));
        float iv = __int_as_float(p.y);
        float2 a = __half22float2(*(__half2*)&u.x), b = __half22float2(*(__half2*)&u.y);
        acc.x = fmaf(a.x, iv, acc.x); acc.y = fmaf(a.y, iv, acc.y);
        acc.z = fmaf(b.x, iv, acc.z); acc.w = fmaf(b.y, iv, acc.w);
    }
    *(float4*)yp = acc;
}

// ---------------- launch ----------------
extern "C" void kernel_launch(void* const* d_in, const int* in_sizes, int n_in,
                              void* d_out, int out_size) {
    const float* x       = (const float*)d_in[0];
    const int*   ei      = (const int*)d_in[1];   // int32 (JAX x64 disabled)
    const int*   et      = (const int*)d_in[2];
    const float* W1_rel  = (const float*)d_in[3];
    const float* W1_root = (const float*)d_in[4];
    const float* b1      = (const float*)d_in[5];
    const float* W2_rel  = (const float*)d_in[6];
    const float* W2_root = (const float*)d_in[7];
    const float* b2      = (const float*)d_in[8];
    float* out = (float*)d_out;

    const int N = in_sizes[0] / INF;
    const int E = in_sizes[2];

    float *h;
    __half *xw;
    int *cnt, *offp, *curp, *bsum;
    int2 *sp;
    __nv_bfloat16 *xhi, *xlo, *bh1, *bl1, *bh2, *bl2;
    cudaGetSymbolAddress((void**)&xw,   g_xw);
    cudaGetSymbolAddress((void**)&h,    g_h);
    cudaGetSymbolAddress((void**)&cnt,  g_cnt);
    cudaGetSymbolAddress((void**)&sp,   g_sp);
    cudaGetSymbolAddress((void**)&offp, g_off);
    cudaGetSymbolAddress((void**)&curp, g_cur);
    cudaGetSymbolAddress((void**)&bsum, g_bsum);
    cudaGetSymbolAddress((void**)&xhi,  g_xhi);
    cudaGetSymbolAddress((void**)&xlo,  g_xlo);
    cudaGetSymbolAddress((void**)&bh1,  g_bhi1);
    cudaGetSymbolAddress((void**)&bl1,  g_blo1);
    cudaGetSymbolAddress((void**)&bh2,  g_bhi2);
    cudaGetSymbolAddress((void**)&bl2,  g_blo2);

    const int SMB = (2 * 128 + 2 * 64) * 72 * 2;  // 55296 B
    cudaFuncSetAttribute(k_mma<128>, cudaFuncAttributeMaxDynamicSharedMemorySize, SMB);
    cudaFuncSetAttribute(k_mma<64>,  cudaFuncAttributeMaxDynamicSharedMemorySize, SMB);

    // high-priority side stream + fork/join events (created once, host-side only)
    static cudaStream_t s1 = nullptr;
    static cudaEvent_t evFork = nullptr, evJoin = nullptr;
    if (!s1) {
        int loPri, hiPri;
        cudaDeviceGetStreamPriorityRange(&loPri, &hiPri);
        cudaStreamCreateWithPriority(&s1, cudaStreamNonBlocking, hiPri);
        cudaEventCreateWithFlags(&evFork, cudaEventDisableTiming);
        cudaEventCreateWithFlags(&evJoin, cudaEventDisableTiming);
    }

    const int nscan = (N + 1023) / 1024;
    dim3 gg((N + 127) / 128, 9);
    const int ab = (N + 15) / 16;

    // ---- fork: CSR build + layer-2 weight split on high-priority s1 ----
    cudaEventRecord(evFork, 0);
    cudaStreamWaitEvent(s1, evFork, 0);

    k_zero_cnt<<<(N * RREL + 255) / 256, 256, 0, s1>>>(cnt, N * RREL);
    k_count<<<(E + 255) / 256, 256, 0, s1>>>(ei, et, cnt, E);
    k_scan_a<<<nscan, 1024, 0, s1>>>(cnt, offp, bsum, N);
    k_scan_b<<<1, 64, 0, s1>>>(bsum, nscan, offp, N);
    k_scan_c<<<nscan, 1024, 0, s1>>>(offp, curp, bsum, N);
    k_permute<<<(E + 255) / 256, 256, 0, s1>>>(ei, et, cnt, curp, sp, E, N);
    k_splitw<<<(9 * 64 * 64 + 255) / 256, 256, 0, s1>>>(W2_rel, W2_root, bh2, bl2, 64);
    cudaEventRecord(evJoin, s1);

    // ---- main stream: layer-1 weight split, input split, transforms ----
    k_splitw<<<(9 * 64 * 128 + 255) / 256, 256>>>(W1_rel, W1_root, bh1, bl1, 128);
    k_split<false><<<(N * 128 / 4 + 255) / 256, 256>>>(x, xhi, xlo, N * 128);
    k_mma<128><<<gg, 256, SMB>>>(xhi, xlo, bh1, bl1, b1, xw, h, N);

    // ---- join: aggregation needs CSR + xw/h ----
    cudaStreamWaitEvent(0, evJoin, 0);
    k_agg<<<ab, 256>>>(offp, sp, xw, h, N);

    // Layer 2: ReLU fused into split; root init of d_out; aggregation
    k_split<true><<<(N * 64 / 4 + 255) / 256, 256>>>(h, xhi, xlo, N * 64);
    k_mma<64><<<gg, 256, SMB>>>(xhi, xlo, bh2, bl2, b2, xw, out, N);
    k_agg<<<ab, 256>>>(offp, sp, xw, out, N);
}